// round 1
// baseline (speedup 1.0000x reference)
#include <cuda_runtime.h>

#define NT 512
#define CC 66
#define TT 100
#define JJ 22
#define HH 8
#define HD 64

// SMEM float offsets
//  sp   [66][100]  : 0      .. 6599
//  tp   [66][100]  : 6600   .. 13199
//  esp  [100][66]  : 13200  .. 19799
//  etp  [66][100]  : 19800  .. 26399
//  Asm  [22][22]   : 26400  .. 26883
//  scr             : 26884  .. 56383   (29500 floats)
//    Qb [100][65] = scr+0, Kb = scr+6500, Vb = scr+13000, Sc [100][100] = scr+19500
#define SMEM_FLOATS 56384

__global__ __launch_bounds__(NT, 1)
void fused_kernel(
    const float* __restrict__ x,
    const float* __restrict__ adj_mask,
    const float* __restrict__ s_adj,
    const float* __restrict__ traj_mask,
    const float* __restrict__ t_adj,
    const float* __restrict__ st_wq, const float* __restrict__ st_bq,
    const float* __restrict__ st_wk, const float* __restrict__ st_bk,
    const float* __restrict__ st_wv, const float* __restrict__ st_bv,
    const float* __restrict__ st_wo, const float* __restrict__ st_bo,
    const float* __restrict__ ts_wq, const float* __restrict__ ts_bq,
    const float* __restrict__ ts_wk, const float* __restrict__ ts_bk,
    const float* __restrict__ ts_wv, const float* __restrict__ ts_bv,
    const float* __restrict__ ts_wo, const float* __restrict__ ts_bo,
    const float* __restrict__ ln_alpha, const float* __restrict__ ln_beta,
    const float* __restrict__ fc_w, const float* __restrict__ fc_b,
    float* __restrict__ out)
{
    extern __shared__ float S[];
    float* sp  = S;            // spatial   [c][t]
    float* tp  = S + 6600;     // temporal  [c][t]
    float* esp = S + 13200;    // enh_sp    [t][c]
    float* etp = S + 19800;    // enh_tp    [c][t]
    float* Asm = S + 26400;    // A         [v][j]
    float* scr = S + 26884;
    float* Qb  = scr;          // [row][65]
    float* Kb  = scr + 6500;
    float* Vb  = scr + 13000;
    float* Sc  = scr + 19500;  // [row][100] scores / weight staging

    const int b   = blockIdx.x;
    const int tid = threadIdx.x;
    const float* xb = x + (size_t)b * (CC * TT);

    // ================= phase 1: x, A, spatial, temporal =================
    {
        float* xs = scr;            // 6600
        float* Ms = scr + 6600;     // 10000
        for (int i = tid; i < CC * TT; i += NT) xs[i] = xb[i];
        for (int i = tid; i < TT * TT; i += NT) Ms[i] = t_adj[i] * traj_mask[i];
        for (int i = tid; i < JJ * JJ; i += NT) {
            int v = i / JJ, j = i % JJ;
            float dv = 0.f, dj = 0.f;
            for (int k = 0; k < JJ; k++) { dv += adj_mask[v * JJ + k]; dj += adj_mask[j * JJ + k]; }
            float iv = dv > 0.f ? rsqrtf(dv) : 0.f;
            float ij = dj > 0.f ? rsqrtf(dj) : 0.f;
            Asm[i] = s_adj[i] * adj_mask[i] * iv * ij;
        }
        __syncthreads();
        // spatial[v*3+d][t] = sum_j A[v][j] * x[(j*3+d)][t]
        for (int i = tid; i < CC * TT; i += NT) {
            int c = i / TT, t = i % TT;
            int v = c / 3, dd = c % 3;
            float acc = 0.f;
            #pragma unroll
            for (int j = 0; j < JJ; j++)
                acc = fmaf(Asm[v * JJ + j], xs[(j * 3 + dd) * TT + t], acc);
            sp[i] = acc;
        }
        // temporal[c][f] = sum_t M[f][t] * x[c][t]
        for (int i = tid; i < CC * TT; i += NT) {
            int c = i / TT, f = i % TT;
            float acc = 0.f;
            #pragma unroll 4
            for (int t = 0; t < TT; t++)
                acc = fmaf(Ms[f * TT + t], xs[c * TT + t], acc);
            tp[i] = acc;
        }
        // init accumulators with output-proj biases
        for (int i = tid; i < TT * CC; i += NT) esp[i] = st_bo[i % CC];
        for (int i = tid; i < CC * TT; i += NT) etp[i] = ts_bo[i % TT];
    }

    const int dl = tid & 63;   // 0..63 (head_dim lane)
    const int g6 = tid >> 6;   // 0..7  (row group)

    for (int h = 0; h < HH; h++) {
        const int eoff = h * HD + dl;

        // =========================== st branch ===========================
        __syncthreads();
        // stage wq_h [66][64]
        for (int i = tid; i < CC * HD; i += NT)
            Sc[i] = st_wq[(i / HD) * 512 + h * HD + (i & 63)];
        __syncthreads();
        // Q_st [100][64]: Q[t][d] = bias + sum_c sp[c][t] * wq[c][d]
        {
            float acc[13];
            float bias = st_bq[eoff];
            #pragma unroll
            for (int k = 0; k < 13; k++) acc[k] = bias;
            #pragma unroll 2
            for (int c = 0; c < CC; c++) {
                float wv = Sc[c * HD + dl];
                const float* r = sp + c * TT;
                #pragma unroll
                for (int k = 0; k < 13; k++) {
                    int t = g6 + (k << 3);
                    if (t < TT) acc[k] = fmaf(r[t], wv, acc[k]);
                }
            }
            #pragma unroll
            for (int k = 0; k < 13; k++) {
                int t = g6 + (k << 3);
                if (t < TT) Qb[t * 65 + dl] = acc[k];
            }
        }
        __syncthreads();
        // stage wk_h [100][64]
        for (int i = tid; i < TT * HD; i += NT)
            Sc[i] = st_wk[(i / HD) * 512 + h * HD + (i & 63)];
        __syncthreads();
        // K_st [66][64]: K[c][d] = bias + sum_f tp[c][f] * wk[f][d]
        {
            float acc[9];
            float bias = st_bk[eoff];
            #pragma unroll
            for (int k = 0; k < 9; k++) acc[k] = bias;
            #pragma unroll 2
            for (int f = 0; f < TT; f++) {
                float wv = Sc[f * HD + dl];
                #pragma unroll
                for (int k = 0; k < 9; k++) {
                    int c = g6 + (k << 3);
                    if (c < CC) acc[k] = fmaf(tp[c * TT + f], wv, acc[k]);
                }
            }
            #pragma unroll
            for (int k = 0; k < 9; k++) {
                int c = g6 + (k << 3);
                if (c < CC) Kb[c * 65 + dl] = acc[k];
            }
        }
        __syncthreads();
        // stage wv_h
        for (int i = tid; i < TT * HD; i += NT)
            Sc[i] = st_wv[(i / HD) * 512 + h * HD + (i & 63)];
        __syncthreads();
        // V_st [66][64]
        {
            float acc[9];
            float bias = st_bv[eoff];
            #pragma unroll
            for (int k = 0; k < 9; k++) acc[k] = bias;
            #pragma unroll 2
            for (int f = 0; f < TT; f++) {
                float wv = Sc[f * HD + dl];
                #pragma unroll
                for (int k = 0; k < 9; k++) {
                    int c = g6 + (k << 3);
                    if (c < CC) acc[k] = fmaf(tp[c * TT + f], wv, acc[k]);
                }
            }
            #pragma unroll
            for (int k = 0; k < 9; k++) {
                int c = g6 + (k << 3);
                if (c < CC) Vb[c * 65 + dl] = acc[k];
            }
        }
        __syncthreads();
        // scores [100][66] = Q K^T / 8
        for (int i = tid; i < TT * CC; i += NT) {
            int q = i / CC, kk = i % CC;
            const float* qr = Qb + q * 65;
            const float* kr = Kb + kk * 65;
            float acc = 0.f;
            #pragma unroll
            for (int d = 0; d < HD; d++) acc = fmaf(qr[d], kr[d], acc);
            Sc[q * TT + kk] = acc * 0.125f;
        }
        __syncthreads();
        // softmax over 66, rows 100 (warp per row)
        {
            int w = tid >> 5, l = tid & 31;
            for (int q = w; q < TT; q += 16) {
                float m = -1e30f;
                for (int k = l; k < CC; k += 32) m = fmaxf(m, Sc[q * TT + k]);
                #pragma unroll
                for (int o = 16; o > 0; o >>= 1) m = fmaxf(m, __shfl_xor_sync(0xffffffffu, m, o));
                float s = 0.f;
                for (int k = l; k < CC; k += 32) { float e = __expf(Sc[q * TT + k] - m); Sc[q * TT + k] = e; s += e; }
                #pragma unroll
                for (int o = 16; o > 0; o >>= 1) s += __shfl_xor_sync(0xffffffffu, s, o);
                float inv = 1.f / s;
                for (int k = l; k < CC; k += 32) Sc[q * TT + k] *= inv;
            }
        }
        __syncthreads();
        // O = P V -> Qb [100][64]
        for (int i = tid; i < TT * HD; i += NT) {
            int q = i >> 6, d = i & 63;
            const float* pr = Sc + q * TT;
            float acc = 0.f;
            #pragma unroll 2
            for (int kk = 0; kk < CC; kk++) acc = fmaf(pr[kk], Vb[kk * 65 + d], acc);
            Qb[q * 65 + d] = acc;
        }
        __syncthreads();
        // stage wo_h [64][66] (contiguous slice)
        for (int i = tid; i < HD * CC; i += NT) Sc[i] = st_wo[h * HD * CC + i];
        __syncthreads();
        // esp[t][c] += sum_d O[t][d] * wo[d][c]
        for (int i = tid; i < TT * CC; i += NT) {
            int t = i / CC, c = i % CC;
            const float* orow = Qb + t * 65;
            float acc = esp[i];
            #pragma unroll
            for (int d = 0; d < HD; d++) acc = fmaf(orow[d], Sc[d * CC + c], acc);
            esp[i] = acc;
        }

        // =========================== ts branch ===========================
        __syncthreads();
        // stage ts_wq_h [100][64]
        for (int i = tid; i < TT * HD; i += NT)
            Sc[i] = ts_wq[(i / HD) * 512 + h * HD + (i & 63)];
        __syncthreads();
        // Q_ts [66][64]: Q[c][d] = bias + sum_t tp[c][t] * wq[t][d]
        {
            float acc[9];
            float bias = ts_bq[eoff];
            #pragma unroll
            for (int k = 0; k < 9; k++) acc[k] = bias;
            #pragma unroll 2
            for (int f = 0; f < TT; f++) {
                float wv = Sc[f * HD + dl];
                #pragma unroll
                for (int k = 0; k < 9; k++) {
                    int c = g6 + (k << 3);
                    if (c < CC) acc[k] = fmaf(tp[c * TT + f], wv, acc[k]);
                }
            }
            #pragma unroll
            for (int k = 0; k < 9; k++) {
                int c = g6 + (k << 3);
                if (c < CC) Qb[c * 65 + dl] = acc[k];
            }
        }
        __syncthreads();
        // stage ts_wk_h [66][64]
        for (int i = tid; i < CC * HD; i += NT)
            Sc[i] = ts_wk[(i / HD) * 512 + h * HD + (i & 63)];
        __syncthreads();
        // K_ts [100][64]: K[t][d] = bias + sum_c sp[c][t] * wk[c][d]
        {
            float acc[13];
            float bias = ts_bk[eoff];
            #pragma unroll
            for (int k = 0; k < 13; k++) acc[k] = bias;
            #pragma unroll 2
            for (int c = 0; c < CC; c++) {
                float wv = Sc[c * HD + dl];
                const float* r = sp + c * TT;
                #pragma unroll
                for (int k = 0; k < 13; k++) {
                    int t = g6 + (k << 3);
                    if (t < TT) acc[k] = fmaf(r[t], wv, acc[k]);
                }
            }
            #pragma unroll
            for (int k = 0; k < 13; k++) {
                int t = g6 + (k << 3);
                if (t < TT) Kb[t * 65 + dl] = acc[k];
            }
        }
        __syncthreads();
        // stage ts_wv_h [66][64]
        for (int i = tid; i < CC * HD; i += NT)
            Sc[i] = ts_wv[(i / HD) * 512 + h * HD + (i & 63)];
        __syncthreads();
        // V_ts [100][64]
        {
            float acc[13];
            float bias = ts_bv[eoff];
            #pragma unroll
            for (int k = 0; k < 13; k++) acc[k] = bias;
            #pragma unroll 2
            for (int c = 0; c < CC; c++) {
                float wv = Sc[c * HD + dl];
                const float* r = sp + c * TT;
                #pragma unroll
                for (int k = 0; k < 13; k++) {
                    int t = g6 + (k << 3);
                    if (t < TT) acc[k] = fmaf(r[t], wv, acc[k]);
                }
            }
            #pragma unroll
            for (int k = 0; k < 13; k++) {
                int t = g6 + (k << 3);
                if (t < TT) { Kb[t * 65 + dl] = Kb[t * 65 + dl]; Vb[t * 65 + dl] = acc[k]; }
            }
        }
        __syncthreads();
        // scores ts [66][100]
        for (int i = tid; i < CC * TT; i += NT) {
            int q = i / TT, kk = i % TT;
            const float* qr = Qb + q * 65;
            const float* kr = Kb + kk * 65;
            float acc = 0.f;
            #pragma unroll
            for (int d = 0; d < HD; d++) acc = fmaf(qr[d], kr[d], acc);
            Sc[q * TT + kk] = acc * 0.125f;
        }
        __syncthreads();
        // softmax over 100, rows 66
        {
            int w = tid >> 5, l = tid & 31;
            for (int q = w; q < CC; q += 16) {
                float m = -1e30f;
                for (int k = l; k < TT; k += 32) m = fmaxf(m, Sc[q * TT + k]);
                #pragma unroll
                for (int o = 16; o > 0; o >>= 1) m = fmaxf(m, __shfl_xor_sync(0xffffffffu, m, o));
                float s = 0.f;
                for (int k = l; k < TT; k += 32) { float e = __expf(Sc[q * TT + k] - m); Sc[q * TT + k] = e; s += e; }
                #pragma unroll
                for (int o = 16; o > 0; o >>= 1) s += __shfl_xor_sync(0xffffffffu, s, o);
                float inv = 1.f / s;
                for (int k = l; k < TT; k += 32) Sc[q * TT + k] *= inv;
            }
        }
        __syncthreads();
        // O = P V -> Qb [66][64]
        for (int i = tid; i < CC * HD; i += NT) {
            int q = i >> 6, d = i & 63;
            const float* pr = Sc + q * TT;
            float acc = 0.f;
            #pragma unroll 2
            for (int kk = 0; kk < TT; kk++) acc = fmaf(pr[kk], Vb[kk * 65 + d], acc);
            Qb[q * 65 + d] = acc;
        }
        __syncthreads();
        // stage ts_wo_h [64][100] (contiguous slice)
        for (int i = tid; i < HD * TT; i += NT) Sc[i] = ts_wo[h * HD * TT + i];
        __syncthreads();
        // etp[c][t] += sum_d O[c][d] * wo[d][t]
        for (int i = tid; i < CC * TT; i += NT) {
            int c = i / TT, t = i % TT;
            const float* orow = Qb + c * 65;
            float acc = etp[i];
            #pragma unroll
            for (int d = 0; d < HD; d++) acc = fmaf(orow[d], Sc[d * TT + t], acc);
            etp[i] = acc;
        }
    }
    __syncthreads();

    // ================= phase 3: LN + residual + fc + tanh =================
    {
        float* xs2 = scr;          // 6600
        float* fw  = scr + 6600;   // [100][101]
        for (int i = tid; i < CC * TT; i += NT) xs2[i] = xb[i];
        for (int i = tid; i < TT * TT; i += NT) { int f = i / TT, t = i % TT; fw[f * 101 + t] = fc_w[i]; }
        __syncthreads();
        if (tid < TT) {
            int t = tid;
            float mean = 0.f;
            for (int c = 0; c < CC; c++) mean += esp[t * CC + c] + etp[c * TT + t];
            mean *= (1.f / 66.f);
            float var = 0.f;
            for (int c = 0; c < CC; c++) {
                float v = esp[t * CC + c] + etp[c * TT + t] - mean;
                var = fmaf(v, v, var);
            }
            var *= (1.f / 66.f);
            float inv = rsqrtf(var + 1e-5f);
            for (int c = 0; c < CC; c++) {
                float v = esp[t * CC + c] + etp[c * TT + t];
                float y = (v - mean) * inv * ln_alpha[c] + ln_beta[c];
                sp[c * TT + t] = y + xs2[c * TT + t];   // z = y + x
            }
        }
        __syncthreads();
        float* outb = out + (size_t)b * (CC * TT);
        for (int i = tid; i < CC * TT; i += NT) {
            int c = i / TT, f = i % TT;
            const float* zr = sp + c * TT;
            const float* fr = fw + f * 101;
            float acc = fc_b[f];
            #pragma unroll 4
            for (int t = 0; t < TT; t++) acc = fmaf(zr[t], fr[t], acc);
            outb[i] = tanhf(acc);
        }
    }
}

extern "C" void kernel_launch(void* const* d_in, const int* in_sizes, int n_in,
                              void* d_out, int out_size) {
    const float* x         = (const float*)d_in[0];
    const float* adj_mask  = (const float*)d_in[1];
    const float* s_adj     = (const float*)d_in[2];
    const float* traj_mask = (const float*)d_in[3];
    const float* t_adj     = (const float*)d_in[4];
    const float* st_wq = (const float*)d_in[5];  const float* st_bq = (const float*)d_in[6];
    const float* st_wk = (const float*)d_in[7];  const float* st_bk = (const float*)d_in[8];
    const float* st_wv = (const float*)d_in[9];  const float* st_bv = (const float*)d_in[10];
    const float* st_wo = (const float*)d_in[11]; const float* st_bo = (const float*)d_in[12];
    const float* ts_wq = (const float*)d_in[13]; const float* ts_bq = (const float*)d_in[14];
    const float* ts_wk = (const float*)d_in[15]; const float* ts_bk = (const float*)d_in[16];
    const float* ts_wv = (const float*)d_in[17]; const float* ts_bv = (const float*)d_in[18];
    const float* ts_wo = (const float*)d_in[19]; const float* ts_bo = (const float*)d_in[20];
    const float* ln_alpha = (const float*)d_in[21];
    const float* ln_beta  = (const float*)d_in[22];
    const float* fc_w     = (const float*)d_in[23];
    const float* fc_b     = (const float*)d_in[24];
    float* out = (float*)d_out;

    int B = in_sizes[0] / (CC * TT);
    size_t smem = (size_t)SMEM_FLOATS * sizeof(float);
    cudaFuncSetAttribute(fused_kernel, cudaFuncAttributeMaxDynamicSharedMemorySize, (int)smem);

    fused_kernel<<<B, NT, smem>>>(
        x, adj_mask, s_adj, traj_mask, t_adj,
        st_wq, st_bq, st_wk, st_bk, st_wv, st_bv, st_wo, st_bo,
        ts_wq, ts_bq, ts_wk, ts_bk, ts_wv, ts_bv, ts_wo, ts_bo,
        ln_alpha, ln_beta, fc_w, fc_b, out);
}

// round 3
// speedup vs baseline: 2.0530x; 2.0530x over previous
#include <cuda_runtime.h>

#define NT 512
#define CC 66
#define TT 100
#define JJ 22
#define HH 8
#define HD 64

// smem float offsets
#define OFF_SP    0        // sp  [66][100]
#define OFF_TPT   6600     // tpT [100][68]
#define OFF_ESP   13400    // esp [100][68]
#define OFF_ETP   20200    // etp [68][104]  (2 pad rows for edge tiles)
#define OFF_ASM   27272    // A   [22][22]
#define OFF_SCR   27760    // scratch region:
#define OFF_QT    27760    //   QT [64][100] / [64][68] / Wo stage   (6400)
#define OFF_KT    34160    //   KT [64][100] / [64][68] / OT         (6400)
#define OFF_V     40560    //   V  [..][64]                          (6400)
#define OFF_STB   46960    //   ST [68][104] scores / W stage        (7072)
#define SMEM_FLOATS 54032

// C[m][n] (+)= scale * sum_k A[k][m] * B[k][n]  (+ biasM[m] + biasN[n])
// 4x4 register tile per thread, float4 loads on both operands.
__device__ __forceinline__ void gemm44(
    const float* __restrict__ A, const int lda,
    const float* __restrict__ B, const int ldb,
    float* __restrict__ C, const int ldc,
    const int Mt, const int Nt, const int K,
    const float* __restrict__ biasM, const float* __restrict__ biasN,
    const float scale, const bool accum, const int tid)
{
    if (tid < Mt * Nt) {
        const int mt = tid / Nt;
        const int m0 = mt << 2;
        const int n0 = (tid - mt * Nt) << 2;
        float bm[4] = {0.f, 0.f, 0.f, 0.f};
        float bn[4] = {0.f, 0.f, 0.f, 0.f};
        if (biasM) {
            bm[0] = biasM[m0]; bm[1] = biasM[m0 + 1];
            bm[2] = biasM[m0 + 2]; bm[3] = biasM[m0 + 3];
        }
        if (biasN) {
            bn[0] = biasN[n0]; bn[1] = biasN[n0 + 1];
            bn[2] = biasN[n0 + 2]; bn[3] = biasN[n0 + 3];
        }
        float acc[4][4];
        #pragma unroll
        for (int i = 0; i < 4; i++)
            #pragma unroll
            for (int j = 0; j < 4; j++) acc[i][j] = 0.f;

        const float* Ap = A + m0;
        const float* Bp = B + n0;
        #pragma unroll 2
        for (int k = 0; k < K; ++k) {
            const float4 av = *(const float4*)Ap;
            const float4 bv = *(const float4*)Bp;
            Ap += lda; Bp += ldb;
            acc[0][0] = fmaf(av.x, bv.x, acc[0][0]);
            acc[0][1] = fmaf(av.x, bv.y, acc[0][1]);
            acc[0][2] = fmaf(av.x, bv.z, acc[0][2]);
            acc[0][3] = fmaf(av.x, bv.w, acc[0][3]);
            acc[1][0] = fmaf(av.y, bv.x, acc[1][0]);
            acc[1][1] = fmaf(av.y, bv.y, acc[1][1]);
            acc[1][2] = fmaf(av.y, bv.z, acc[1][2]);
            acc[1][3] = fmaf(av.y, bv.w, acc[1][3]);
            acc[2][0] = fmaf(av.z, bv.x, acc[2][0]);
            acc[2][1] = fmaf(av.z, bv.y, acc[2][1]);
            acc[2][2] = fmaf(av.z, bv.z, acc[2][2]);
            acc[2][3] = fmaf(av.z, bv.w, acc[2][3]);
            acc[3][0] = fmaf(av.w, bv.x, acc[3][0]);
            acc[3][1] = fmaf(av.w, bv.y, acc[3][1]);
            acc[3][2] = fmaf(av.w, bv.z, acc[3][2]);
            acc[3][3] = fmaf(av.w, bv.w, acc[3][3]);
        }
        #pragma unroll
        for (int i = 0; i < 4; i++) {
            float4 r;
            r.x = fmaf(acc[i][0], scale, bm[i] + bn[0]);
            r.y = fmaf(acc[i][1], scale, bm[i] + bn[1]);
            r.z = fmaf(acc[i][2], scale, bm[i] + bn[2]);
            r.w = fmaf(acc[i][3], scale, bm[i] + bn[3]);
            float* cp = C + (m0 + i) * ldc + n0;
            if (accum) {
                const float4 o = *(const float4*)cp;
                r.x += o.x; r.y += o.y; r.z += o.z; r.w += o.w;
            }
            *(float4*)cp = r;
        }
    }
}

// softmax over the row index (k) for each column q of M[k][q], ld stride
__device__ __forceinline__ void softmax_cols(float* __restrict__ M, const int ld,
                                             const int R, const int Qn, const int tid)
{
    const int w = tid >> 5, l = tid & 31;
    for (int q = w; q < Qn; q += 16) {
        float mx = -1e30f;
        for (int r = l; r < R; r += 32) mx = fmaxf(mx, M[r * ld + q]);
        #pragma unroll
        for (int o = 16; o > 0; o >>= 1) mx = fmaxf(mx, __shfl_xor_sync(0xffffffffu, mx, o));
        float s = 0.f;
        for (int r = l; r < R; r += 32) {
            const float e = __expf(M[r * ld + q] - mx);
            M[r * ld + q] = e; s += e;
        }
        #pragma unroll
        for (int o = 16; o > 0; o >>= 1) s += __shfl_xor_sync(0xffffffffu, s, o);
        const float inv = 1.f / s;
        for (int r = l; r < R; r += 32) M[r * ld + q] *= inv;
    }
}

__global__ __launch_bounds__(NT, 1)
void fused_kernel(
    const float* __restrict__ x,
    const float* __restrict__ adj_mask,
    const float* __restrict__ s_adj,
    const float* __restrict__ traj_mask,
    const float* __restrict__ t_adj,
    const float* __restrict__ st_wq, const float* __restrict__ st_bq,
    const float* __restrict__ st_wk, const float* __restrict__ st_bk,
    const float* __restrict__ st_wv, const float* __restrict__ st_bv,
    const float* __restrict__ st_wo, const float* __restrict__ st_bo,
    const float* __restrict__ ts_wq, const float* __restrict__ ts_bq,
    const float* __restrict__ ts_wk, const float* __restrict__ ts_bk,
    const float* __restrict__ ts_wv, const float* __restrict__ ts_bv,
    const float* __restrict__ ts_wo, const float* __restrict__ ts_bo,
    const float* __restrict__ ln_alpha, const float* __restrict__ ln_beta,
    const float* __restrict__ fc_w, const float* __restrict__ fc_b,
    float* __restrict__ out)
{
    extern __shared__ float S[];
    float* SP  = S + OFF_SP;
    float* TPT = S + OFF_TPT;
    float* ESP = S + OFF_ESP;
    float* ETP = S + OFF_ETP;
    float* ASM = S + OFF_ASM;
    float* QT  = S + OFF_QT;
    float* KT  = S + OFF_KT;
    float* V   = S + OFF_V;
    float* STB = S + OFF_STB;

    const int b   = blockIdx.x;
    const int tid = threadIdx.x;
    const float* xb = x + (size_t)b * (CC * TT);

    // ================= phase 1 =================
    {
        float* xs = S + OFF_SCR;           // [66][100]
        float* Ms = S + OFF_SCR + 6600;    // [100][100]
        for (int i = tid; i < CC * TT; i += NT) xs[i] = xb[i];
        for (int i = tid; i < TT * TT; i += NT) Ms[i] = t_adj[i] * traj_mask[i];
        for (int i = tid; i < JJ * JJ; i += NT) {
            const int v = i / JJ, j = i % JJ;
            float dv = 0.f, dj = 0.f;
            for (int k = 0; k < JJ; k++) { dv += adj_mask[v * JJ + k]; dj += adj_mask[j * JJ + k]; }
            const float iv = dv > 0.f ? rsqrtf(dv) : 0.f;
            const float ij = dj > 0.f ? rsqrtf(dj) : 0.f;
            ASM[i] = s_adj[i] * adj_mask[i] * iv * ij;
        }
        __syncthreads();
        // spatial
        for (int i = tid; i < CC * TT; i += NT) {
            const int c = i / TT, t = i % TT;
            const int v = c / 3, dd = c % 3;
            float acc = 0.f;
            #pragma unroll
            for (int j = 0; j < JJ; j++)
                acc = fmaf(ASM[v * JJ + j], xs[(j * 3 + dd) * TT + t], acc);
            SP[i] = acc;
        }
        // temporal, written transposed: tpT[f][c]
        for (int i = tid; i < TT * CC; i += NT) {
            const int f = i / CC, c = i % CC;
            const float4* mr = (const float4*)(Ms + f * TT);
            const float4* xr = (const float4*)(xs + c * TT);
            float acc = 0.f;
            #pragma unroll 5
            for (int k = 0; k < TT / 4; k++) {
                const float4 m4 = mr[k], x4 = xr[k];
                acc = fmaf(m4.x, x4.x, acc);
                acc = fmaf(m4.y, x4.y, acc);
                acc = fmaf(m4.z, x4.z, acc);
                acc = fmaf(m4.w, x4.w, acc);
            }
            TPT[f * 68 + c] = acc;
        }
        // init accumulators (padded regions -> 0)
        for (int i = tid; i < TT * 68; i += NT) {
            const int c = i % 68;
            ESP[i] = (c < CC) ? st_bo[c] : 0.f;
        }
        for (int i = tid; i < 68 * 104; i += NT) {
            const int c = i / 104, t = i % 104;
            ETP[i] = (c < CC && t < TT) ? ts_bo[t] : 0.f;
        }
    }

    for (int h = 0; h < HH; h++) {
        const int ho = h << 6;
        // ======== st branch ========
        __syncthreads();
        for (int i = tid; i < CC * HD; i += NT)
            STB[i] = st_wq[(i >> 6) * 512 + ho + (i & 63)];
        __syncthreads();
        // QT[d][t] = sum_c W[c][d]*sp[c][t] + bq[d]
        gemm44(STB, 64, SP, 100, QT, 100, 16, 25, CC, st_bq + ho, nullptr, 1.f, false, tid);
        __syncthreads();
        for (int i = tid; i < TT * HD; i += NT)
            STB[i] = st_wk[(i >> 6) * 512 + ho + (i & 63)];
        __syncthreads();
        // KT[d][c] = sum_f W[f][d]*tpT[f][c] + bk[d]
        gemm44(STB, 64, TPT, 68, KT, 100, 16, 17, TT, st_bk + ho, nullptr, 1.f, false, tid);
        __syncthreads();
        for (int i = tid; i < TT * HD; i += NT)
            STB[i] = st_wv[(i >> 6) * 512 + ho + (i & 63)];
        __syncthreads();
        // V[c][d] = sum_f tpT[f][c]*W[f][d] + bv[d]
        gemm44(TPT, 68, STB, 64, V, 64, 17, 16, TT, nullptr, st_bv + ho, 1.f, false, tid);
        __syncthreads();
        // scores ST[kk][q] = 0.125 * sum_d KT[d][kk]*QT[d][q]
        gemm44(KT, 100, QT, 100, STB, 104, 17, 25, HD, nullptr, nullptr, 0.125f, false, tid);
        __syncthreads();
        softmax_cols(STB, 104, CC, TT, tid);
        __syncthreads();
        // OT[d][q] = sum_k V[k][d]*ST[k][q]  -> KT buffer
        gemm44(V, 64, STB, 104, KT, 100, 16, 25, CC, nullptr, nullptr, 1.f, false, tid);
        __syncthreads();
        for (int i = tid; i < HD * CC; i += NT)
            QT[(i / CC) * 68 + (i % CC)] = st_wo[h * (HD * CC) + i];
        __syncthreads();
        // esp[t][c] += sum_d OT[d][t]*Wo[d][c]
        gemm44(KT, 100, QT, 68, ESP, 68, 25, 17, HD, nullptr, nullptr, 1.f, true, tid);

        // ======== ts branch ========
        __syncthreads();
        for (int i = tid; i < TT * HD; i += NT)
            STB[i] = ts_wq[(i >> 6) * 512 + ho + (i & 63)];
        __syncthreads();
        // QT[d][c] = sum_f W[f][d]*tpT[f][c] + bq[d]
        gemm44(STB, 64, TPT, 68, QT, 68, 16, 17, TT, ts_bq + ho, nullptr, 1.f, false, tid);
        __syncthreads();
        for (int i = tid; i < CC * HD; i += NT)
            STB[i] = ts_wk[(i >> 6) * 512 + ho + (i & 63)];
        __syncthreads();
        // KT[d][t] = sum_c W[c][d]*sp[c][t] + bk[d]
        gemm44(STB, 64, SP, 100, KT, 100, 16, 25, CC, ts_bk + ho, nullptr, 1.f, false, tid);
        __syncthreads();
        for (int i = tid; i < CC * HD; i += NT)
            STB[i] = ts_wv[(i >> 6) * 512 + ho + (i & 63)];
        __syncthreads();
        // V[t][d] = sum_c sp[c][t]*W[c][d] + bv[d]
        gemm44(SP, 100, STB, 64, V, 64, 25, 16, CC, nullptr, ts_bv + ho, 1.f, false, tid);
        __syncthreads();
        // scores ST[t][c] = 0.125 * sum_d KT[d][t]*QT[d][c]
        gemm44(KT, 100, QT, 68, STB, 68, 25, 17, HD, nullptr, nullptr, 0.125f, false, tid);
        __syncthreads();
        softmax_cols(STB, 68, TT, CC, tid);
        __syncthreads();
        // OT[d][c] = sum_t V[t][d]*ST[t][c] -> KT buffer
        gemm44(V, 64, STB, 68, KT, 68, 16, 17, TT, nullptr, nullptr, 1.f, false, tid);
        __syncthreads();
        for (int i = tid; i < HD * TT; i += NT)
            QT[i] = ts_wo[h * (HD * TT) + i];
        __syncthreads();
        // etp[c][t] += sum_d OT[d][c]*Wo[d][t]
        gemm44(KT, 68, QT, 100, ETP, 104, 17, 25, HD, nullptr, nullptr, 1.f, true, tid);
    }
    __syncthreads();

    // ================= phase 3 =================
    {
        float* fw  = S + OFF_SCR;          // [100][100]
        float* xs2 = S + OFF_SCR + 10000;  // [66][100]
        for (int i = tid; i < TT * TT; i += NT) fw[i] = fc_w[i];
        for (int i = tid; i < CC * TT; i += NT) xs2[i] = xb[i];
        __syncthreads();
        if (tid < TT) {
            const int t = tid;
            float mean = 0.f;
            for (int c = 0; c < CC; c++) mean += ESP[t * 68 + c] + ETP[c * 104 + t];
            mean *= (1.f / 66.f);
            float var = 0.f;
            for (int c = 0; c < CC; c++) {
                const float v = ESP[t * 68 + c] + ETP[c * 104 + t] - mean;
                var = fmaf(v, v, var);
            }
            var *= (1.f / 66.f);
            const float inv = rsqrtf(var + 1e-5f);
            for (int c = 0; c < CC; c++) {
                const float v = ESP[t * 68 + c] + ETP[c * 104 + t];
                const float y = (v - mean) * inv * ln_alpha[c] + ln_beta[c];
                SP[c * TT + t] = y + xs2[c * TT + t];
            }
        }
        __syncthreads();
        float* outb = out + (size_t)b * (CC * TT);
        for (int i = tid; i < CC * TT; i += NT) {
            const int c = i / TT, f = i % TT;
            const float4* zr = (const float4*)(SP + c * TT);
            const float4* fr = (const float4*)(fw + f * TT);
            float acc = fc_b[f];
            #pragma unroll 5
            for (int k = 0; k < TT / 4; k++) {
                const float4 z4 = zr[k], f4 = fr[k];
                acc = fmaf(z4.x, f4.x, acc);
                acc = fmaf(z4.y, f4.y, acc);
                acc = fmaf(z4.z, f4.z, acc);
                acc = fmaf(z4.w, f4.w, acc);
            }
            outb[i] = tanhf(acc);
        }
    }
}

extern "C" void kernel_launch(void* const* d_in, const int* in_sizes, int n_in,
                              void* d_out, int out_size) {
    const float* x         = (const float*)d_in[0];
    const float* adj_mask  = (const float*)d_in[1];
    const float* s_adj     = (const float*)d_in[2];
    const float* traj_mask = (const float*)d_in[3];
    const float* t_adj     = (const float*)d_in[4];
    const float* st_wq = (const float*)d_in[5];  const float* st_bq = (const float*)d_in[6];
    const float* st_wk = (const float*)d_in[7];  const float* st_bk = (const float*)d_in[8];
    const float* st_wv = (const float*)d_in[9];  const float* st_bv = (const float*)d_in[10];
    const float* st_wo = (const float*)d_in[11]; const float* st_bo = (const float*)d_in[12];
    const float* ts_wq = (const float*)d_in[13]; const float* ts_bq = (const float*)d_in[14];
    const float* ts_wk = (const float*)d_in[15]; const float* ts_bk = (const float*)d_in[16];
    const float* ts_wv = (const float*)d_in[17]; const float* ts_bv = (const float*)d_in[18];
    const float* ts_wo = (const float*)d_in[19]; const float* ts_bo = (const float*)d_in[20];
    const float* ln_alpha = (const float*)d_in[21];
    const float* ln_beta  = (const float*)d_in[22];
    const float* fc_w     = (const float*)d_in[23];
    const float* fc_b     = (const float*)d_in[24];
    float* out = (float*)d_out;

    const int B = in_sizes[0] / (CC * TT);
    const size_t smem = (size_t)SMEM_FLOATS * sizeof(float);
    cudaFuncSetAttribute(fused_kernel, cudaFuncAttributeMaxDynamicSharedMemorySize, (int)smem);

    fused_kernel<<<B, NT, smem>>>(
        x, adj_mask, s_adj, traj_mask, t_adj,
        st_wq, st_bq, st_wk, st_bk, st_wv, st_bv, st_wo, st_bo,
        ts_wq, ts_bq, ts_wk, ts_bk, ts_wv, ts_bv, ts_wo, ts_bo,
        ln_alpha, ln_beta, fc_w, fc_b, out);
}

// round 6
// speedup vs baseline: 2.4953x; 1.2154x over previous
#include <cuda_runtime.h>

#define NT 512
#define CC 66
#define TT 100
#define JJ 22
#define HH 8
#define HD 64

// smem float offsets (all multiples of 4 -> 16B aligned)
#define OFF_SP   0        // sp  [66][100]                          6600
#define OFF_TPT  6600     // tpT [100][68]                          6800
#define OFF_ESP  13400    // esp [104][68]                          7072
#define OFF_ETP  20472    // etp [72][104]                          7488
#define OFF_QT   27960    // QT / Wo stage / phase scratch          6400
#define OFF_KT   34360    // KT / OT                                6400
#define OFF_V    40760    // V [104][64]                            6656
#define OFF_STB  47416    // ST [72][104] or [104][68] / W stage    7488
#define OFF_ASM  54904    // A  [22][22]                            484
#define OFF_RED  55388    // softmax partials [8][104]              832
#define SMEM_FLOATS 56220

__device__ __forceinline__ unsigned long long pk2(float lo, float hi) {
    unsigned long long r;
    asm("mov.b64 %0, {%1, %2};" : "=l"(r) : "f"(lo), "f"(hi));
    return r;
}
__device__ __forceinline__ void upk2(float& lo, float& hi, unsigned long long v) {
    asm("mov.b64 {%0, %1}, %2;" : "=f"(lo), "=f"(hi) : "l"(v));
}
__device__ __forceinline__ void fma2(unsigned long long& acc, unsigned long long a,
                                     unsigned long long b) {
    asm("fma.rn.f32x2 %0, %1, %2, %0;" : "+l"(acc) : "l"(a), "l"(b));
}

// C[m][n] (+)= scale * sum_k A[k][m]*B[k][n] (+ biasM[m] + biasN[n])
// 8x4 register tile, packed f32x2 FMA. Pair dim = m (pairs come free from LDS.128 quads).
__device__ __forceinline__ void gemm84(
    const float* __restrict__ A, const int lda,
    const float* __restrict__ B, const int ldb,
    float* __restrict__ C, const int ldc,
    const int Mt, const int Nt, const int K,
    const float* __restrict__ biasM, const float* __restrict__ biasN,
    const float scale, const bool accum, const int tid)
{
    if (tid >= Mt * Nt) return;
    const int mt = tid / Nt;
    const int m0 = mt << 3;
    const int n0 = (tid - mt * Nt) << 2;

    unsigned long long acc[4][4];   // [m-pair][n]
    #pragma unroll
    for (int i = 0; i < 4; i++)
        #pragma unroll
        for (int j = 0; j < 4; j++) acc[i][j] = 0ull;

    const float* Ap = A + m0;
    const float* Bp = B + n0;
    #pragma unroll 2
    for (int k = 0; k < K; ++k) {
        const float4 a0 = *(const float4*)Ap;
        const float4 a1 = *(const float4*)(Ap + 4);
        const float4 bv = *(const float4*)Bp;
        Ap += lda; Bp += ldb;
        const unsigned long long ap0 = pk2(a0.x, a0.y);
        const unsigned long long ap1 = pk2(a0.z, a0.w);
        const unsigned long long ap2 = pk2(a1.x, a1.y);
        const unsigned long long ap3 = pk2(a1.z, a1.w);
        const unsigned long long b0 = pk2(bv.x, bv.x);
        const unsigned long long b1 = pk2(bv.y, bv.y);
        const unsigned long long b2 = pk2(bv.z, bv.z);
        const unsigned long long b3 = pk2(bv.w, bv.w);
        fma2(acc[0][0], ap0, b0); fma2(acc[1][0], ap1, b0);
        fma2(acc[2][0], ap2, b0); fma2(acc[3][0], ap3, b0);
        fma2(acc[0][1], ap0, b1); fma2(acc[1][1], ap1, b1);
        fma2(acc[2][1], ap2, b1); fma2(acc[3][1], ap3, b1);
        fma2(acc[0][2], ap0, b2); fma2(acc[1][2], ap1, b2);
        fma2(acc[2][2], ap2, b2); fma2(acc[3][2], ap3, b2);
        fma2(acc[0][3], ap0, b3); fma2(acc[1][3], ap1, b3);
        fma2(acc[2][3], ap2, b3); fma2(acc[3][3], ap3, b3);
    }

    float bn[4] = {0.f, 0.f, 0.f, 0.f};
    if (biasN) { bn[0] = biasN[n0]; bn[1] = biasN[n0+1]; bn[2] = biasN[n0+2]; bn[3] = biasN[n0+3]; }
    #pragma unroll
    for (int i2 = 0; i2 < 4; i2++) {
        float lo[4], hi[4];
        #pragma unroll
        for (int j = 0; j < 4; j++) upk2(lo[j], hi[j], acc[i2][j]);
        const int mA = m0 + (i2 << 1);
        float bmA = 0.f, bmB = 0.f;
        if (biasM) { bmA = biasM[mA]; bmB = biasM[mA + 1]; }
        float4 rA, rB;
        rA.x = fmaf(lo[0], scale, bmA + bn[0]);
        rA.y = fmaf(lo[1], scale, bmA + bn[1]);
        rA.z = fmaf(lo[2], scale, bmA + bn[2]);
        rA.w = fmaf(lo[3], scale, bmA + bn[3]);
        rB.x = fmaf(hi[0], scale, bmB + bn[0]);
        rB.y = fmaf(hi[1], scale, bmB + bn[1]);
        rB.z = fmaf(hi[2], scale, bmB + bn[2]);
        rB.w = fmaf(hi[3], scale, bmB + bn[3]);
        float* cA = C + mA * ldc + n0;
        float* cB = cA + ldc;
        if (accum) {
            const float4 oA = *(const float4*)cA;
            const float4 oB = *(const float4*)cB;
            rA.x += oA.x; rA.y += oA.y; rA.z += oA.z; rA.w += oA.w;
            rB.x += oB.x; rB.y += oB.y; rB.z += oB.z; rB.w += oB.w;
        }
        *(float4*)cA = rA;
        *(float4*)cB = rB;
    }
}

// two-level softmax over rows (k) for each column q of M[k][q].
// lane = column (conflict-free LDS); 4 warps per 32-col chunk split the rows.
// Needs all NT threads to participate (contains __syncthreads).
__device__ __forceinline__ void softmax2(float* __restrict__ M, const int ld,
                                         const int R, const int Qn,
                                         float* __restrict__ red, const int tid)
{
    const int w = tid >> 5, l = tid & 31;
    const int chunk = w & 3;          // which 32-column chunk
    const int quarter = w >> 2;       // which row quarter
    const int q = (chunk << 5) + l;
    const int rlo = (R * quarter) >> 2;
    const int rhi = (R * (quarter + 1)) >> 2;
    const bool act = (q < Qn);

    float mx = -1e30f;
    if (act) for (int r = rlo; r < rhi; r++) mx = fmaxf(mx, M[r * ld + q]);
    if (act) red[quarter * 104 + q] = mx;
    __syncthreads();
    float gm = 0.f;
    if (act) gm = fmaxf(fmaxf(red[q], red[104 + q]), fmaxf(red[208 + q], red[312 + q]));
    float s = 0.f;
    if (act) {
        for (int r = rlo; r < rhi; r++) {
            const float e = __expf(M[r * ld + q] - gm);
            M[r * ld + q] = e; s += e;
        }
    }
    __syncthreads();
    if (act) red[416 + quarter * 104 + q] = s;
    __syncthreads();
    if (act) {
        const float inv = 1.f / (red[416 + q] + red[520 + q] + red[624 + q] + red[728 + q]);
        for (int r = rlo; r < rhi; r++) M[r * ld + q] *= inv;
    }
}

__global__ __launch_bounds__(NT, 1)
void fused_kernel(
    const float* __restrict__ x,
    const float* __restrict__ adj_mask,
    const float* __restrict__ s_adj,
    const float* __restrict__ traj_mask,
    const float* __restrict__ t_adj,
    const float* __restrict__ st_wq, const float* __restrict__ st_bq,
    const float* __restrict__ st_wk, const float* __restrict__ st_bk,
    const float* __restrict__ st_wv, const float* __restrict__ st_bv,
    const float* __restrict__ st_wo, const float* __restrict__ st_bo,
    const float* __restrict__ ts_wq, const float* __restrict__ ts_bq,
    const float* __restrict__ ts_wk, const float* __restrict__ ts_bk,
    const float* __restrict__ ts_wv, const float* __restrict__ ts_bv,
    const float* __restrict__ ts_wo, const float* __restrict__ ts_bo,
    const float* __restrict__ ln_alpha, const float* __restrict__ ln_beta,
    const float* __restrict__ fc_w, const float* __restrict__ fc_b,
    float* __restrict__ out)
{
    extern __shared__ float S[];
    float* SP  = S + OFF_SP;
    float* TPT = S + OFF_TPT;
    float* ESP = S + OFF_ESP;
    float* ETP = S + OFF_ETP;
    float* QT  = S + OFF_QT;
    float* KT  = S + OFF_KT;
    float* V   = S + OFF_V;
    float* STB = S + OFF_STB;
    float* ASM = S + OFF_ASM;
    float* RED = S + OFF_RED;

    const int b   = blockIdx.x;
    const int tid = threadIdx.x;
    const float* xb = x + (size_t)b * (CC * TT);

    // ================= phase 1 =================
    {
        float* xs = QT;            // [66][100]
        float* Ms = QT + 6600;     // [100][100] (spans into KT/V scratch)
        for (int i = tid; i < CC * TT; i += NT) xs[i] = xb[i];
        for (int i = tid; i < TT * TT; i += NT) Ms[i] = t_adj[i] * traj_mask[i];
        for (int i = tid; i < JJ * JJ; i += NT) {
            const int v = i / JJ, j = i % JJ;
            float dv = 0.f, dj = 0.f;
            for (int k = 0; k < JJ; k++) { dv += adj_mask[v * JJ + k]; dj += adj_mask[j * JJ + k]; }
            const float iv = dv > 0.f ? rsqrtf(dv) : 0.f;
            const float ij = dj > 0.f ? rsqrtf(dj) : 0.f;
            ASM[i] = s_adj[i] * adj_mask[i] * iv * ij;
        }
        __syncthreads();
        // spatial
        for (int i = tid; i < CC * TT; i += NT) {
            const int c = i / TT, t = i % TT;
            const int v = c / 3, dd = c % 3;
            float acc = 0.f;
            #pragma unroll
            for (int j = 0; j < JJ; j++)
                acc = fmaf(ASM[v * JJ + j], xs[(j * 3 + dd) * TT + t], acc);
            SP[i] = acc;
        }
        // temporal, transposed: tpT[f][c]  (f32x2 dot products)
        for (int i = tid; i < TT * 68; i += NT) {
            const int f = i / 68, c = i % 68;
            if (c >= CC) { TPT[i] = 0.f; continue; }
            const float4* mr = (const float4*)(Ms + f * TT);
            const float4* xr = (const float4*)(xs + c * TT);
            unsigned long long a01 = 0ull, a23 = 0ull;
            #pragma unroll 5
            for (int k = 0; k < TT / 4; k++) {
                const float4 m4 = mr[k], x4 = xr[k];
                fma2(a01, pk2(m4.x, m4.y), pk2(x4.x, x4.y));
                fma2(a23, pk2(m4.z, m4.w), pk2(x4.z, x4.w));
            }
            float l0, h0, l1, h1;
            upk2(l0, h0, a01); upk2(l1, h1, a23);
            TPT[i] = (l0 + h0) + (l1 + h1);
        }
        // init accumulators (padded regions -> 0)
        for (int i = tid; i < 104 * 68; i += NT) {
            const int c = i % 68;
            ESP[i] = (c < CC) ? st_bo[c] : 0.f;
        }
        for (int i = tid; i < 72 * 104; i += NT) {
            const int c = i / 104, t = i % 104;
            ETP[i] = (c < CC && t < TT) ? ts_bo[t] : 0.f;
        }
    }

    for (int h = 0; h < HH; h++) {
        const int ho = h << 6;
        // ======== st branch ========
        __syncthreads();
        for (int i = tid; i < CC * HD; i += NT)
            STB[i] = st_wq[(i >> 6) * 512 + ho + (i & 63)];
        __syncthreads();
        // QT[d][t] = sum_c W[c][d]*sp[c][t] + bq[d]    (M=64,N=100,K=66)
        gemm84(STB, 64, SP, 100, QT, 100, 8, 25, CC, st_bq + ho, nullptr, 1.f, false, tid);
        __syncthreads();
        for (int i = tid; i < TT * HD; i += NT)
            STB[i] = st_wk[(i >> 6) * 512 + ho + (i & 63)];
        __syncthreads();
        // KT[d][c] = sum_f W[f][d]*tpT[f][c] + bk[d]   (M=64,N=66,K=100)
        gemm84(STB, 64, TPT, 68, KT, 100, 8, 17, TT, st_bk + ho, nullptr, 1.f, false, tid);
        __syncthreads();
        for (int i = tid; i < TT * HD; i += NT)
            STB[i] = st_wv[(i >> 6) * 512 + ho + (i & 63)];
        __syncthreads();
        // V[c][d] = sum_f tpT[f][c]*W[f][d] + bv[d]    (M=66,N=64,K=100)
        gemm84(TPT, 68, STB, 64, V, 64, 9, 16, TT, nullptr, st_bv + ho, 1.f, false, tid);
        __syncthreads();
        // ST[kk][q] = 0.125 * sum_d KT[d][kk]*QT[d][q] (M=66,N=100,K=64)
        gemm84(KT, 100, QT, 100, STB, 104, 9, 25, HD, nullptr, nullptr, 0.125f, false, tid);
        __syncthreads();
        softmax2(STB, 104, CC, TT, RED, tid);
        __syncthreads();
        // OT[d][q] = sum_k V[k][d]*ST[k][q] -> KT       (M=64,N=100,K=66)
        gemm84(V, 64, STB, 104, KT, 100, 8, 25, CC, nullptr, nullptr, 1.f, false, tid);
        __syncthreads();
        for (int i = tid; i < HD * CC; i += NT)
            QT[(i / CC) * 68 + (i % CC)] = st_wo[h * (HD * CC) + i];
        __syncthreads();
        // esp[t][c] += sum_d OT[d][t]*Wo[d][c]          (M=100,N=66,K=64)
        gemm84(KT, 100, QT, 68, ESP, 68, 13, 17, HD, nullptr, nullptr, 1.f, true, tid);

        // ======== ts branch ========
        __syncthreads();
        for (int i = tid; i < TT * HD; i += NT)
            STB[i] = ts_wq[(i >> 6) * 512 + ho + (i & 63)];
        __syncthreads();
        // QT[d][c] = sum_f W[f][d]*tpT[f][c] + bq[d]   (M=64,N=66,K=100)
        gemm84(STB, 64, TPT, 68, QT, 68, 8, 17, TT, ts_bq + ho, nullptr, 1.f, false, tid);
        __syncthreads();
        for (int i = tid; i < CC * HD; i += NT)
            STB[i] = ts_wk[(i >> 6) * 512 + ho + (i & 63)];
        __syncthreads();
        // KT[d][t] = sum_c W[c][d]*sp[c][t] + bk[d]    (M=64,N=100,K=66)
        gemm84(STB, 64, SP, 100, KT, 100, 8, 25, CC, ts_bk + ho, nullptr, 1.f, false, tid);
        __syncthreads();
        for (int i = tid; i < CC * HD; i += NT)
            STB[i] = ts_wv[(i >> 6) * 512 + ho + (i & 63)];
        __syncthreads();
        // V[t][d] = sum_c sp[c][t]*W[c][d] + bv[d]     (M=100,N=64,K=66)
        gemm84(SP, 100, STB, 64, V, 64, 13, 16, CC, nullptr, ts_bv + ho, 1.f, false, tid);
        __syncthreads();
        // ST[t][c] = 0.125 * sum_d KT[d][t]*QT[d][c]   (M=100,N=66,K=64)
        gemm84(KT, 100, QT, 68, STB, 68, 13, 17, HD, nullptr, nullptr, 0.125f, false, tid);
        __syncthreads();
        softmax2(STB, 68, TT, CC, RED, tid);
        __syncthreads();
        // OT[d][c] = sum_t V[t][d]*ST[t][c] -> KT       (M=64,N=66,K=100)
        gemm84(V, 64, STB, 68, KT, 68, 8, 17, TT, nullptr, nullptr, 1.f, false, tid);
        __syncthreads();
        for (int i = tid; i < HD * TT; i += NT)
            QT[i] = ts_wo[h * (HD * TT) + i];
        __syncthreads();
        // etp[c][t] += sum_d OT[d][c]*Wo[d][t]          (M=66,N=100,K=64)
        gemm84(KT, 68, QT, 100, ETP, 104, 9, 25, HD, nullptr, nullptr, 1.f, true, tid);
    }
    __syncthreads();

    // ================= phase 3 =================
    {
        float* fw  = QT;           // [100][100] (spans QT+KT)
        float* xs2 = V;            // [66][100]
        for (int i = tid; i < TT * TT; i += NT) fw[i] = fc_w[i];
        for (int i = tid; i < CC * TT; i += NT) xs2[i] = xb[i];
        __syncthreads();
        if (tid < TT) {
            const int t = tid;
            float mean = 0.f;
            for (int c = 0; c < CC; c++) mean += ESP[t * 68 + c] + ETP[c * 104 + t];
            mean *= (1.f / 66.f);
            float var = 0.f;
            for (int c = 0; c < CC; c++) {
                const float v = ESP[t * 68 + c] + ETP[c * 104 + t] - mean;
                var = fmaf(v, v, var);
            }
            var *= (1.f / 66.f);
            const float inv = rsqrtf(var + 1e-5f);
            for (int c = 0; c < CC; c++) {
                const float v = ESP[t * 68 + c] + ETP[c * 104 + t];
                const float y = (v - mean) * inv * ln_alpha[c] + ln_beta[c];
                SP[c * TT + t] = y + xs2[c * TT + t];
            }
        }
        __syncthreads();
        float* outb = out + (size_t)b * (CC * TT);
        for (int i = tid; i < CC * TT; i += NT) {
            const int c = i / TT, f = i % TT;
            const float4* zr = (const float4*)(SP + c * TT);
            const float4* fr = (const float4*)(fw + f * TT);
            unsigned long long a01 = 0ull, a23 = 0ull;
            #pragma unroll 5
            for (int k = 0; k < TT / 4; k++) {
                const float4 z4 = zr[k], f4 = fr[k];
                fma2(a01, pk2(z4.x, z4.y), pk2(f4.x, f4.y));
                fma2(a23, pk2(z4.z, z4.w), pk2(f4.z, f4.w));
            }
            float l0, h0, l1, h1;
            upk2(l0, h0, a01); upk2(l1, h1, a23);
            outb[i] = tanhf(fc_b[f] + (l0 + h0) + (l1 + h1));
        }
    }
}

extern "C" void kernel_launch(void* const* d_in, const int* in_sizes, int n_in,
                              void* d_out, int out_size) {
    const float* x         = (const float*)d_in[0];
    const float* adj_mask  = (const float*)d_in[1];
    const float* s_adj     = (const float*)d_in[2];
    const float* traj_mask = (const float*)d_in[3];
    const float* t_adj     = (const float*)d_in[4];
    const float* st_wq = (const float*)d_in[5];  const float* st_bq = (const float*)d_in[6];
    const float* st_wk = (const float*)d_in[7];  const float* st_bk = (const float*)d_in[8];
    const float* st_wv = (const float*)d_in[9];  const float* st_bv = (const float*)d_in[10];
    const float* st_wo = (const float*)d_in[11]; const float* st_bo = (const float*)d_in[12];
    const float* ts_wq = (const float*)d_in[13]; const float* ts_bq = (const float*)d_in[14];
    const float* ts_wk = (const float*)d_in[15]; const float* ts_bk = (const float*)d_in[16];
    const float* ts_wv = (const float*)d_in[17]; const float* ts_bv = (const float*)d_in[18];
    const float* ts_wo = (const float*)d_in[19]; const float* ts_bo = (const float*)d_in[20];
    const float* ln_alpha = (const float*)d_in[21];
    const float* ln_beta  = (const float*)d_in[22];
    const float* fc_w     = (const float*)d_in[23];
    const float* fc_b     = (const float*)d_in[24];
    float* out = (float*)d_out;

    const int B = in_sizes[0] / (CC * TT);
    const size_t smem = (size_t)SMEM_FLOATS * sizeof(float);
    cudaFuncSetAttribute(fused_kernel, cudaFuncAttributeMaxDynamicSharedMemorySize, (int)smem);

    fused_kernel<<<B, NT, smem>>>(
        x, adj_mask, s_adj, traj_mask, t_adj,
        st_wq, st_bq, st_wk, st_bk, st_wv, st_bv, st_wo, st_bo,
        ts_wq, ts_bq, ts_wk, ts_bk, ts_wv, ts_bv, ts_wo, ts_bo,
        ln_alpha, ln_beta, fc_w, fc_b, out);
}